// round 15
// baseline (speedup 1.0000x reference)
#include <cuda_runtime.h>
#include <cuda_bf16.h>
#include <cstdint>

// Problem constants
#define B_  2
#define T_  2048
#define C_  768
#define H_  12
#define DH_ 64
#define C3_ 2304                 // 3*C
#define GROWB 4608               // 3*C * sizeof(bf16) bytes per qkv row

// ---------------------------------------------------------------------------
// Scratch (allocation-free: __device__ globals)
// ---------------------------------------------------------------------------
__device__ __align__(16) __nv_bfloat16 g_xh[(size_t)B_ * T_ * C_];
__device__ __align__(16) __nv_bfloat16 g_xl[(size_t)B_ * T_ * C_];
__device__ __align__(16) __nv_bfloat16 g_qkvh[(size_t)B_ * T_ * C3_];
__device__ __align__(16) __nv_bfloat16 g_qkvl[(size_t)B_ * T_ * C3_];
__device__ __align__(16) __nv_bfloat16 g_ah[(size_t)B_ * T_ * C_];
__device__ __align__(16) __nv_bfloat16 g_al[(size_t)B_ * T_ * C_];
__device__ __align__(16) __nv_bfloat16 g_wqTh[(size_t)3 * C_ * C_];   // Wqkv^T [3C, C]
__device__ __align__(16) __nv_bfloat16 g_wqTl[(size_t)3 * C_ * C_];
__device__ __align__(16) __nv_bfloat16 g_woTh[(size_t)C_ * C_];       // Wout^T [C, C]
__device__ __align__(16) __nv_bfloat16 g_woTl[(size_t)C_ * C_];

// ---------------------------------------------------------------------------
// Baseline-ISA helpers (sm_80-class: cp.async, ldmatrix, mma.sync)
// ---------------------------------------------------------------------------
__device__ __forceinline__ uint32_t smem_u32(const void* p) {
    uint32_t a;
    asm("{ .reg .u64 t; cvta.to.shared.u64 t, %1; cvt.u32.u64 %0, t; }"
        : "=r"(a) : "l"(p));
    return a;
}
__device__ __forceinline__ float ex2(float x) {
    float r;
    asm("ex2.approx.ftz.f32 %0, %1;" : "=f"(r) : "f"(x));
    return r;
}

#define CP_ASYNC16(sm, gp) \
    asm volatile("cp.async.cg.shared.global [%0], [%1], 16;" \
                 :: "r"(sm), "l"(gp) : "memory")
#define CP_COMMIT() asm volatile("cp.async.commit_group;" ::: "memory")
#define CP_WAIT(n)  asm volatile("cp.async.wait_group %0;" :: "n"(n) : "memory")

#define LDSM_X4(f, addr) \
    asm volatile("ldmatrix.sync.aligned.m8n8.x4.shared.b16 {%0,%1,%2,%3}, [%4];" \
                 : "=r"((f)[0]), "=r"((f)[1]), "=r"((f)[2]), "=r"((f)[3]) \
                 : "r"(addr))

#define LDSM_X4_T(f, addr) \
    asm volatile("ldmatrix.sync.aligned.m8n8.x4.trans.shared.b16 {%0,%1,%2,%3}, [%4];" \
                 : "=r"((f)[0]), "=r"((f)[1]), "=r"((f)[2]), "=r"((f)[3]) \
                 : "r"(addr))

#define MMA16816(d, a, b0, b1) \
    asm volatile("mma.sync.aligned.m16n8k16.row.col.f32.bf16.bf16.f32 " \
                 "{%0,%1,%2,%3}, {%4,%5,%6,%7}, {%8,%9}, {%0,%1,%2,%3};" \
                 : "+f"((d)[0]), "+f"((d)[1]), "+f"((d)[2]), "+f"((d)[3]) \
                 : "r"((a)[0]), "r"((a)[1]), "r"((a)[2]), "r"((a)[3]), \
                   "r"(b0), "r"(b1))

#define SWZ64(o) ((o) ^ (((o) >> 3) & 0x30))

// fp32 pair -> bf16x2 hi + bf16x2 lo residual
__device__ __forceinline__ void split2(float a, float b, uint32_t& hi, uint32_t& lo) {
    __nv_bfloat162 h = __floats2bfloat162_rn(a, b);
    float2 hf = __bfloat1622float2(h);
    __nv_bfloat162 l2 = __floats2bfloat162_rn(a - hf.x, b - hf.y);
    hi = *(uint32_t*)&h;
    lo = *(uint32_t*)&l2;
}

// ---------------------------------------------------------------------------
// Elementwise fp32 -> (bf16 hi, bf16 lo) split
// ---------------------------------------------------------------------------
__global__ void split_bf16(const float* __restrict__ in,
                           __nv_bfloat16* __restrict__ hi,
                           __nv_bfloat16* __restrict__ lo, int n) {
    int i = blockIdx.x * blockDim.x + threadIdx.x;
    if (i < n) {
        float v = in[i];
        __nv_bfloat16 h = __float2bfloat16(v);
        hi[i] = h;
        lo[i] = __float2bfloat16(v - __bfloat162float(h));
    }
}

// ---------------------------------------------------------------------------
// W[K,N] fp32 -> W^T[N,K] (bf16 hi, bf16 lo)
// ---------------------------------------------------------------------------
__global__ __launch_bounds__(256) void transpose_split(const float* __restrict__ W,
                                                       __nv_bfloat16* __restrict__ Th,
                                                       __nv_bfloat16* __restrict__ Tl,
                                                       int K, int N) {
    __shared__ float t[32][33];
    int n0 = blockIdx.x * 32, k0 = blockIdx.y * 32;
    int tx = threadIdx.x, ty = threadIdx.y;
#pragma unroll
    for (int j = 0; j < 32; j += 8)
        t[ty + j][tx] = W[(size_t)(k0 + ty + j) * N + n0 + tx];
    __syncthreads();
#pragma unroll
    for (int j = 0; j < 32; j += 8) {
        float v = t[tx][ty + j];
        __nv_bfloat16 h = __float2bfloat16(v);
        size_t o = (size_t)(n0 + ty + j) * K + k0 + tx;
        Th[o] = h;
        Tl[o] = __float2bfloat16(v - __bfloat162float(h));
    }
}

// ---------------------------------------------------------------------------
// Warp-MMA GEMM, bf16-split x3:  C = A[M,K] * Bt[N,K]^T  (unchanged, passing)
// OUT_SPLIT=1 applies 0.125*log2e to q columns (attention runs in exp2 domain)
// ---------------------------------------------------------------------------
#define GOFF_AH 0
#define GOFF_AL 8192
#define GOFF_BH 16384
#define GOFF_BL 24576
#define GBUF    32768
#define GSMEM_BYTES (3 * GBUF + 1024)
#define QSCALE  0.18033688f   // 0.125 * log2(e)

template <int OUT_SPLIT>
__global__ __launch_bounds__(256, 2)
void gemm_wmma(const __nv_bfloat16* __restrict__ Ah, const __nv_bfloat16* __restrict__ Al,
               const __nv_bfloat16* __restrict__ Bh, const __nv_bfloat16* __restrict__ Bl,
               float* __restrict__ Cf,
               __nv_bfloat16* __restrict__ Ch, __nv_bfloat16* __restrict__ Cl,
               int M, int N, int K) {
    extern __shared__ char dsm[];
    const int tid = threadIdx.x;
    const int wid = tid >> 5;
    const int lane = tid & 31;
    const int wm = wid & 3;
    const int wn = wid >> 2;
    const int bm = blockIdx.y * 128;
    const int bn = blockIdx.x * 128;

    uint32_t rawb = smem_u32(dsm);
    uint32_t sb = (rawb + 1023u) & ~1023u;

    const int mat = lane >> 3;
    const int lr = lane & 7;
    const int aRow0 = wm * 32 + (mat & 1) * 8 + lr;
    const int aKoff = (mat >> 1) * 16;
    const int bRow0 = wn * 64 + (mat >> 1) * 8 + lr;
    const int bKoff = (mat & 1) * 16;

    float acc[2][8][4];
#pragma unroll
    for (int mt = 0; mt < 2; mt++)
#pragma unroll
        for (int nt = 0; nt < 8; nt++)
#pragma unroll
            for (int e = 0; e < 4; e++) acc[mt][nt][e] = 0.f;

    const int nch = K >> 5;

#define LOAD_CHUNK(bufbase, k0_)                                                   \
    do {                                                                           \
        const char* gah = (const char*)(Ah + (size_t)bm * K + (k0_));              \
        const char* gal = (const char*)(Al + (size_t)bm * K + (k0_));              \
        const char* gbh = (const char*)(Bh + (size_t)bn * K + (k0_));              \
        const char* gbl = (const char*)(Bl + (size_t)bn * K + (k0_));              \
        _Pragma("unroll")                                                          \
        for (int i_ = 0; i_ < 2; i_++) {                                           \
            int idx_ = tid + i_ * 256;                                             \
            int row_ = idx_ >> 2;                                                  \
            int cc_ = idx_ & 3;                                                    \
            uint32_t so_ = SWZ64((uint32_t)(row_ * 64 + cc_ * 16));                \
            size_t go_ = (size_t)row_ * K * 2 + cc_ * 16;                          \
            CP_ASYNC16((bufbase) + GOFF_AH + so_, gah + go_);                      \
            CP_ASYNC16((bufbase) + GOFF_AL + so_, gal + go_);                      \
            CP_ASYNC16((bufbase) + GOFF_BH + so_, gbh + go_);                      \
            CP_ASYNC16((bufbase) + GOFF_BL + so_, gbl + go_);                      \
        }                                                                          \
    } while (0)

    LOAD_CHUNK(sb, 0);
    CP_COMMIT();
    LOAD_CHUNK(sb + GBUF, 32);
    CP_COMMIT();

    for (int c = 0; c < nch; c++) {
        if (c + 1 < nch) { CP_WAIT(1); } else { CP_WAIT(0); }
        __syncthreads();
        if (c + 2 < nch) {
            int nb = (c + 2) % 3;
            LOAD_CHUNK(sb + nb * GBUF, (c + 2) << 5);
            CP_COMMIT();
        }

        const uint32_t cbuf = sb + (c % 3) * GBUF;
#pragma unroll
        for (int ks = 0; ks < 2; ks++) {
            uint32_t afh[2][4], afl[2][4], bfh[4][4], bfl[4][4];
#pragma unroll
            for (int mt = 0; mt < 2; mt++) {
                uint32_t off = SWZ64((uint32_t)((aRow0 + mt * 16) * 64 + ks * 32 + aKoff));
                LDSM_X4(afh[mt], cbuf + GOFF_AH + off);
                LDSM_X4(afl[mt], cbuf + GOFF_AL + off);
            }
#pragma unroll
            for (int np = 0; np < 4; np++) {
                uint32_t off = SWZ64((uint32_t)((bRow0 + np * 16) * 64 + ks * 32 + bKoff));
                LDSM_X4(bfh[np], cbuf + GOFF_BH + off);
                LDSM_X4(bfl[np], cbuf + GOFF_BL + off);
            }
            // term-major passes: same-acc reuse distance = 16
#pragma unroll
            for (int mt = 0; mt < 2; mt++)
#pragma unroll
                for (int nt = 0; nt < 8; nt++) {
                    const int np = nt >> 1, s = (nt & 1) * 2;
                    MMA16816(acc[mt][nt], afh[mt], bfh[np][s], bfh[np][s + 1]);
                }
#pragma unroll
            for (int mt = 0; mt < 2; mt++)
#pragma unroll
                for (int nt = 0; nt < 8; nt++) {
                    const int np = nt >> 1, s = (nt & 1) * 2;
                    MMA16816(acc[mt][nt], afh[mt], bfl[np][s], bfl[np][s + 1]);
                }
#pragma unroll
            for (int mt = 0; mt < 2; mt++)
#pragma unroll
                for (int nt = 0; nt < 8; nt++) {
                    const int np = nt >> 1, s = (nt & 1) * 2;
                    MMA16816(acc[mt][nt], afl[mt], bfh[np][s], bfh[np][s + 1]);
                }
        }
    }

    const int erow = bm + wm * 32 + (lane >> 2);
    const int ecol = bn + wn * 64 + (lane & 3) * 2;
#pragma unroll
    for (int mt = 0; mt < 2; mt++)
#pragma unroll
        for (int nt = 0; nt < 8; nt++) {
            if (OUT_SPLIT) {
                const float sc = (ecol + nt * 8 < C_) ? QSCALE : 1.0f;
                uint32_t hi, lo;
                size_t o0 = (size_t)(erow + mt * 16) * N + ecol + nt * 8;
                split2(acc[mt][nt][0] * sc, acc[mt][nt][1] * sc, hi, lo);
                *(uint32_t*)(Ch + o0) = hi;
                *(uint32_t*)(Cl + o0) = lo;
                split2(acc[mt][nt][2] * sc, acc[mt][nt][3] * sc, hi, lo);
                *(uint32_t*)(Ch + o0 + (size_t)8 * N) = hi;
                *(uint32_t*)(Cl + o0 + (size_t)8 * N) = lo;
            } else {
                float* p = Cf + (size_t)(erow + mt * 16) * N + ecol + nt * 8;
                *(float2*)p = make_float2(acc[mt][nt][0], acc[mt][nt][1]);
                *(float2*)(p + (size_t)8 * N) = make_float2(acc[mt][nt][2], acc[mt][nt][3]);
            }
        }
#undef LOAD_CHUNK
}

// ---------------------------------------------------------------------------
// Flash attention, mma.sync bf16 split x3, HIGH-OCCUPANCY version:
//   256 thr, 8 warps x 16 rows; Q stays RESIDENT in smem (fragments
//   re-loaded per tile — no 64-reg hoist), 2-stage KV ring staged AFTER the
//   barrier (race-free). smem = 36.9 + 2*36.9 = 110.6 KB -> 2 CTAs/SM,
//   16 warps/SM: other warps' MMAs cover each warp's softmax serial chain.
//   Live set ~105 regs — fits the 128-reg cap without spilling (R11 failed
//   at ~170 because of hoisted Q).
// ---------------------------------------------------------------------------
#define RS   144
#define AT_QH   0
#define AT_QL   18432
#define AT_KV0  36864
#define AT_KH   0
#define AT_KL   9216
#define AT_VH   18432
#define AT_VL   27648
#define AT_KVBUF 36864
#define AT_SMEM_ALLOC (AT_KV0 + 2 * AT_KVBUF + 1024)   // 111616 -> 2 CTAs/SM

__global__ __launch_bounds__(256, 2)
void attn_mma(const __nv_bfloat16* __restrict__ qh, const __nv_bfloat16* __restrict__ ql,
              __nv_bfloat16* __restrict__ oh, __nv_bfloat16* __restrict__ ol) {
    extern __shared__ char dsm[];
    const int tid = threadIdx.x;
    const int wid = tid >> 5;
    const int l = tid & 31;
    const int qi = 15 - (int)blockIdx.x;        // longest first
    const int h = blockIdx.y;
    const int b = blockIdx.z;

    uint32_t sb = (smem_u32(dsm) + 1023u) & ~1023u;

    const size_t gq0 = ((size_t)(b * T_ + qi * 128) * C3_ + h * DH_) * 2;  // byte off
    const char* gqh = (const char*)qh + gq0;
    const char* gql = (const char*)ql + gq0;

    // Stage Q (128 rows x 128B), hi + lo -> group 0 (stays resident)
#pragma unroll
    for (int i = 0; i < 4; i++) {
        int idx = tid + i * 256;
        int row = idx >> 3;
        int c = (idx & 7) * 16;
        CP_ASYNC16(sb + AT_QH + row * RS + c, gqh + (size_t)row * GROWB + c);
        CP_ASYNC16(sb + AT_QL + row * RS + c, gql + (size_t)row * GROWB + c);
    }
    CP_COMMIT();

    const int nkt = 2 * qi + 2;   // >= 2

#define STAGE_KV(kt_, buf_)                                                        \
    do {                                                                           \
        uint32_t base_ = sb + AT_KV0 + (buf_) * AT_KVBUF;                          \
        size_t g0_ = ((size_t)(b * T_ + (kt_) * 64) * C3_ + h * DH_ + C_) * 2;     \
        const char* gkh_ = (const char*)qh + g0_;                                  \
        const char* gkl_ = (const char*)ql + g0_;                                  \
        _Pragma("unroll")                                                          \
        for (int i_ = 0; i_ < 2; i_++) {                                           \
            int idx_ = tid + i_ * 256;                                             \
            int row_ = idx_ >> 3;                                                  \
            int c_ = (idx_ & 7) * 16;                                              \
            size_t go_ = (size_t)row_ * GROWB + c_;                                \
            CP_ASYNC16(base_ + AT_KH + row_ * RS + c_, gkh_ + go_);                \
            CP_ASYNC16(base_ + AT_KL + row_ * RS + c_, gkl_ + go_);                \
            CP_ASYNC16(base_ + AT_VH + row_ * RS + c_, gkh_ + go_ + 2 * C_);       \
            CP_ASYNC16(base_ + AT_VL + row_ * RS + c_, gkl_ + go_ + 2 * C_);       \
        }                                                                          \
    } while (0)

    STAGE_KV(0, 0);
    CP_COMMIT();

    float so[8][4], oacc[8][4];
    float m0 = -1e30f, m1 = -1e30f, l0 = 0.f, l1 = 0.f;
#pragma unroll
    for (int nt = 0; nt < 8; nt++)
#pragma unroll
        for (int e = 0; e < 4; e++) oacc[nt][e] = 0.f;

    // ldmatrix address components
    const int mat = l >> 3;
    const uint32_t aAddr0 = sb + AT_QH + (wid * 16 + (mat & 1) * 8 + (l & 7)) * RS + (mat >> 1) * 16;
    const uint32_t bRow = (mat >> 1) * 8 + (l & 7);      // + np*16 rows
    const uint32_t bKo = (mat & 1) * 16;
    const uint32_t vRow = l & 15;                         // + ks*16 rows
    const uint32_t vCo = (l >> 4) * 16;                   // + np*32 bytes

    for (int kt = 0; kt < nkt; kt++) {
        // group(kt) is the only pending cp.async group (Q included at kt=0)
        CP_WAIT(0);
        __syncthreads();   // all warps done reading buf (kt+1)&1 from iter kt-1
        if (kt + 1 < nkt) {
            STAGE_KV(kt + 1, (kt + 1) & 1);
            CP_COMMIT();
        }
        const uint32_t kvb = sb + AT_KV0 + (kt & 1) * AT_KVBUF;

        // ---- S = Q K^T (x3 split); Q frags re-loaded from resident smem ----
#pragma unroll
        for (int nt = 0; nt < 8; nt++)
#pragma unroll
            for (int e = 0; e < 4; e++) so[nt][e] = 0.f;

#pragma unroll
        for (int ks = 0; ks < 4; ks++) {
            uint32_t aqh[4], aql[4];
            LDSM_X4(aqh, aAddr0 + ks * 32);
            LDSM_X4(aql, aAddr0 + ks * 32 + (AT_QL - AT_QH));
#pragma unroll
            for (int np = 0; np < 4; np++) {
                uint32_t bh[4], bl[4];
                uint32_t off = kvb + (np * 16 + bRow) * RS + ks * 32 + bKo;
                LDSM_X4(bh, off + AT_KH);
                LDSM_X4(bl, off + AT_KL);
                MMA16816(so[2 * np], aqh, bh[0], bh[1]);
                MMA16816(so[2 * np + 1], aqh, bh[2], bh[3]);
                MMA16816(so[2 * np], aqh, bl[0], bl[1]);
                MMA16816(so[2 * np + 1], aqh, bl[2], bl[3]);
                MMA16816(so[2 * np], aql, bh[0], bh[1]);
                MMA16816(so[2 * np + 1], aql, bh[2], bh[3]);
            }
        }

        // ---- causal mask (only diagonal tiles) ----
        if (kt >= 2 * qi) {
            const int rg0 = qi * 128 + wid * 16 + (l >> 2);
            const int kg0 = kt * 64 + (l & 3) * 2;
#pragma unroll
            for (int nt = 0; nt < 8; nt++) {
#pragma unroll
                for (int e = 0; e < 4; e++) {
                    int kg = kg0 + nt * 8 + (e & 1);
                    int rg = rg0 + ((e >> 1) << 3);
                    if (kg > rg) so[nt][e] = -1e30f;
                }
            }
        }

        // ---- online softmax, exp2 domain (scale folded into Q) ----
        float mx0 = -1e30f, mx1 = -1e30f;
#pragma unroll
        for (int nt = 0; nt < 8; nt++) {
            mx0 = fmaxf(mx0, fmaxf(so[nt][0], so[nt][1]));
            mx1 = fmaxf(mx1, fmaxf(so[nt][2], so[nt][3]));
        }
        mx0 = fmaxf(mx0, __shfl_xor_sync(0xffffffffu, mx0, 1));
        mx0 = fmaxf(mx0, __shfl_xor_sync(0xffffffffu, mx0, 2));
        mx1 = fmaxf(mx1, __shfl_xor_sync(0xffffffffu, mx1, 1));
        mx1 = fmaxf(mx1, __shfl_xor_sync(0xffffffffu, mx1, 2));
        const float mn0 = fmaxf(m0, mx0), mn1 = fmaxf(m1, mx1);
        const float al0 = ex2(m0 - mn0);
        const float al1 = ex2(m1 - mn1);
        m0 = mn0; m1 = mn1;

        float ps0 = 0.f, ps1 = 0.f;
#pragma unroll
        for (int nt = 0; nt < 8; nt++) {
            so[nt][0] = ex2(so[nt][0] - mn0);
            so[nt][1] = ex2(so[nt][1] - mn0);
            so[nt][2] = ex2(so[nt][2] - mn1);
            so[nt][3] = ex2(so[nt][3] - mn1);
            ps0 += so[nt][0] + so[nt][1];
            ps1 += so[nt][2] + so[nt][3];
        }
        ps0 += __shfl_xor_sync(0xffffffffu, ps0, 1);
        ps0 += __shfl_xor_sync(0xffffffffu, ps0, 2);
        ps1 += __shfl_xor_sync(0xffffffffu, ps1, 1);
        ps1 += __shfl_xor_sync(0xffffffffu, ps1, 2);
        l0 = l0 * al0 + ps0;
        l1 = l1 * al1 + ps1;
#pragma unroll
        for (int nt = 0; nt < 8; nt++) {
            oacc[nt][0] *= al0; oacc[nt][1] *= al0;
            oacc[nt][2] *= al1; oacc[nt][3] *= al1;
        }

        // ---- O += P V (x3 split; P from registers) ----
#pragma unroll
        for (int ks = 0; ks < 4; ks++) {
            uint32_t ph[4], pl[4];
            split2(so[2 * ks][0], so[2 * ks][1], ph[0], pl[0]);
            split2(so[2 * ks][2], so[2 * ks][3], ph[1], pl[1]);
            split2(so[2 * ks + 1][0], so[2 * ks + 1][1], ph[2], pl[2]);
            split2(so[2 * ks + 1][2], so[2 * ks + 1][3], ph[3], pl[3]);
#pragma unroll
            for (int np = 0; np < 4; np++) {
                uint32_t vh[4], vl[4];
                uint32_t off = kvb + (ks * 16 + vRow) * RS + np * 32 + vCo;
                LDSM_X4_T(vh, off + AT_VH);
                LDSM_X4_T(vl, off + AT_VL);
                MMA16816(oacc[2 * np], ph, vh[0], vh[1]);
                MMA16816(oacc[2 * np + 1], ph, vh[2], vh[3]);
                MMA16816(oacc[2 * np], ph, vl[0], vl[1]);
                MMA16816(oacc[2 * np + 1], ph, vl[2], vl[3]);
                MMA16816(oacc[2 * np], pl, vh[0], vh[1]);
                MMA16816(oacc[2 * np + 1], pl, vh[2], vh[3]);
            }
        }
    }

    // ---- normalize + write output pre-split (bf16 hi/lo) ----
    const float i0 = 1.0f / l0, i1 = 1.0f / l1;
    const int row0 = b * T_ + qi * 128 + wid * 16 + (l >> 2);
    const int col = h * DH_ + (l & 3) * 2;
#pragma unroll
    for (int nt = 0; nt < 8; nt++) {
        uint32_t hi, lo;
        size_t o0 = (size_t)row0 * C_ + col + nt * 8;
        split2(oacc[nt][0] * i0, oacc[nt][1] * i0, hi, lo);
        *(uint32_t*)(oh + o0) = hi;
        *(uint32_t*)(ol + o0) = lo;
        split2(oacc[nt][2] * i1, oacc[nt][3] * i1, hi, lo);
        *(uint32_t*)(oh + o0 + (size_t)8 * C_) = hi;
        *(uint32_t*)(ol + o0 + (size_t)8 * C_) = lo;
    }
#undef STAGE_KV
}

// ---------------------------------------------------------------------------
extern "C" void kernel_launch(void* const* d_in, const int* in_sizes, int n_in,
                              void* d_out, int out_size) {
    const float* x = nullptr;
    const float* Wqkv = nullptr;
    const float* Wout = nullptr;
    for (int i = 0; i < n_in; i++) {
        if (in_sizes[i] == B_ * T_ * C_)     x = (const float*)d_in[i];
        else if (in_sizes[i] == C_ * 3 * C_) Wqkv = (const float*)d_in[i];
        else if (in_sizes[i] == C_ * C_)     Wout = (const float*)d_in[i];
    }
    float* out = (float*)d_out;

    __nv_bfloat16 *xh, *xl, *qvh, *qvl, *ah, *al, *wqh, *wql, *woh, *wol;
    cudaGetSymbolAddress((void**)&xh, g_xh);
    cudaGetSymbolAddress((void**)&xl, g_xl);
    cudaGetSymbolAddress((void**)&qvh, g_qkvh);
    cudaGetSymbolAddress((void**)&qvl, g_qkvl);
    cudaGetSymbolAddress((void**)&ah, g_ah);
    cudaGetSymbolAddress((void**)&al, g_al);
    cudaGetSymbolAddress((void**)&wqh, g_wqTh);
    cudaGetSymbolAddress((void**)&wql, g_wqTl);
    cudaGetSymbolAddress((void**)&woh, g_woTh);
    cudaGetSymbolAddress((void**)&wol, g_woTl);

    cudaFuncSetAttribute(gemm_wmma<0>, cudaFuncAttributeMaxDynamicSharedMemorySize, GSMEM_BYTES);
    cudaFuncSetAttribute(gemm_wmma<1>, cudaFuncAttributeMaxDynamicSharedMemorySize, GSMEM_BYTES);
    cudaFuncSetAttribute(attn_mma, cudaFuncAttributeMaxDynamicSharedMemorySize, AT_SMEM_ALLOC);

    const int nx = B_ * T_ * C_;

    // 0) input split + weight transpose-splits
    split_bf16<<<(nx + 255) / 256, 256>>>(x, xh, xl, nx);
    transpose_split<<<dim3((3 * C_) / 32, C_ / 32), dim3(32, 8)>>>(Wqkv, wqh, wql, C_, 3 * C_);
    transpose_split<<<dim3(C_ / 32, C_ / 32), dim3(32, 8)>>>(Wout, woh, wol, C_, C_);

    // 1) QKV projection, bf16 hi/lo output, q block pre-scaled by 0.125*log2e
    gemm_wmma<1><<<dim3((3 * C_) / 128, (B_ * T_) / 128), 256, GSMEM_BYTES>>>(
        xh, xl, wqh, wql, nullptr, qvh, qvl, B_ * T_, 3 * C_, C_);

    // 2) Causal flash attention on tensor cores; emits pre-split output
    attn_mma<<<dim3(T_ / 128, H_, B_), 256, AT_SMEM_ALLOC>>>(qvh, qvl, ah, al);

    // 3) Output projection, fp32 out
    gemm_wmma<0><<<dim3(C_ / 128, (B_ * T_) / 128), 256, GSMEM_BYTES>>>(
        ah, al, woh, wol, out, nullptr, nullptr, B_ * T_, C_, C_);
}

// round 16
// speedup vs baseline: 1.0517x; 1.0517x over previous
#include <cuda_runtime.h>
#include <cuda_bf16.h>
#include <cstdint>

// Problem constants
#define B_  2
#define T_  2048
#define C_  768
#define H_  12
#define DH_ 64
#define C3_ 2304                 // 3*C
#define GROWB 4608               // 3*C * sizeof(bf16) bytes per qkv row

// ---------------------------------------------------------------------------
// Scratch (allocation-free: __device__ globals)
// ---------------------------------------------------------------------------
__device__ __align__(16) __nv_bfloat16 g_xh[(size_t)B_ * T_ * C_];
__device__ __align__(16) __nv_bfloat16 g_xl[(size_t)B_ * T_ * C_];
__device__ __align__(16) __nv_bfloat16 g_qkvh[(size_t)B_ * T_ * C3_];
__device__ __align__(16) __nv_bfloat16 g_qkvl[(size_t)B_ * T_ * C3_];
__device__ __align__(16) __nv_bfloat16 g_ah[(size_t)B_ * T_ * C_];
__device__ __align__(16) __nv_bfloat16 g_al[(size_t)B_ * T_ * C_];
__device__ __align__(16) __nv_bfloat16 g_wqTh[(size_t)3 * C_ * C_];   // Wqkv^T [3C, C]
__device__ __align__(16) __nv_bfloat16 g_wqTl[(size_t)3 * C_ * C_];
__device__ __align__(16) __nv_bfloat16 g_woTh[(size_t)C_ * C_];       // Wout^T [C, C]
__device__ __align__(16) __nv_bfloat16 g_woTl[(size_t)C_ * C_];

// ---------------------------------------------------------------------------
// Baseline-ISA helpers (sm_80-class: cp.async, ldmatrix, mma.sync)
// ---------------------------------------------------------------------------
__device__ __forceinline__ uint32_t smem_u32(const void* p) {
    uint32_t a;
    asm("{ .reg .u64 t; cvta.to.shared.u64 t, %1; cvt.u32.u64 %0, t; }"
        : "=r"(a) : "l"(p));
    return a;
}
__device__ __forceinline__ float ex2(float x) {
    float r;
    asm("ex2.approx.ftz.f32 %0, %1;" : "=f"(r) : "f"(x));
    return r;
}

#define CP_ASYNC16(sm, gp) \
    asm volatile("cp.async.cg.shared.global [%0], [%1], 16;" \
                 :: "r"(sm), "l"(gp) : "memory")
#define CP_COMMIT() asm volatile("cp.async.commit_group;" ::: "memory")
#define CP_WAIT(n)  asm volatile("cp.async.wait_group %0;" :: "n"(n) : "memory")

#define LDSM_X4(f, addr) \
    asm volatile("ldmatrix.sync.aligned.m8n8.x4.shared.b16 {%0,%1,%2,%3}, [%4];" \
                 : "=r"((f)[0]), "=r"((f)[1]), "=r"((f)[2]), "=r"((f)[3]) \
                 : "r"(addr))

#define LDSM_X4_T(f, addr) \
    asm volatile("ldmatrix.sync.aligned.m8n8.x4.trans.shared.b16 {%0,%1,%2,%3}, [%4];" \
                 : "=r"((f)[0]), "=r"((f)[1]), "=r"((f)[2]), "=r"((f)[3]) \
                 : "r"(addr))

#define MMA16816(d, a, b0, b1) \
    asm volatile("mma.sync.aligned.m16n8k16.row.col.f32.bf16.bf16.f32 " \
                 "{%0,%1,%2,%3}, {%4,%5,%6,%7}, {%8,%9}, {%0,%1,%2,%3};" \
                 : "+f"((d)[0]), "+f"((d)[1]), "+f"((d)[2]), "+f"((d)[3]) \
                 : "r"((a)[0]), "r"((a)[1]), "r"((a)[2]), "r"((a)[3]), \
                   "r"(b0), "r"(b1))

#define SWZ64(o) ((o) ^ (((o) >> 3) & 0x30))

// fp32 pair -> bf16x2 hi + bf16x2 lo residual
__device__ __forceinline__ void split2(float a, float b, uint32_t& hi, uint32_t& lo) {
    __nv_bfloat162 h = __floats2bfloat162_rn(a, b);
    float2 hf = __bfloat1622float2(h);
    __nv_bfloat162 l2 = __floats2bfloat162_rn(a - hf.x, b - hf.y);
    hi = *(uint32_t*)&h;
    lo = *(uint32_t*)&l2;
}

// ---------------------------------------------------------------------------
// Elementwise fp32 -> (bf16 hi, bf16 lo) split
// ---------------------------------------------------------------------------
__global__ void split_bf16(const float* __restrict__ in,
                           __nv_bfloat16* __restrict__ hi,
                           __nv_bfloat16* __restrict__ lo, int n) {
    int i = blockIdx.x * blockDim.x + threadIdx.x;
    if (i < n) {
        float v = in[i];
        __nv_bfloat16 h = __float2bfloat16(v);
        hi[i] = h;
        lo[i] = __float2bfloat16(v - __bfloat162float(h));
    }
}

// ---------------------------------------------------------------------------
// W[K,N] fp32 -> W^T[N,K] (bf16 hi, bf16 lo)
// ---------------------------------------------------------------------------
__global__ __launch_bounds__(256) void transpose_split(const float* __restrict__ W,
                                                       __nv_bfloat16* __restrict__ Th,
                                                       __nv_bfloat16* __restrict__ Tl,
                                                       int K, int N) {
    __shared__ float t[32][33];
    int n0 = blockIdx.x * 32, k0 = blockIdx.y * 32;
    int tx = threadIdx.x, ty = threadIdx.y;
#pragma unroll
    for (int j = 0; j < 32; j += 8)
        t[ty + j][tx] = W[(size_t)(k0 + ty + j) * N + n0 + tx];
    __syncthreads();
#pragma unroll
    for (int j = 0; j < 32; j += 8) {
        float v = t[tx][ty + j];
        __nv_bfloat16 h = __float2bfloat16(v);
        size_t o = (size_t)(n0 + ty + j) * K + k0 + tx;
        Th[o] = h;
        Tl[o] = __float2bfloat16(v - __bfloat162float(h));
    }
}

// ---------------------------------------------------------------------------
// Warp-MMA GEMM, bf16-split x3:  C = A[M,K] * Bt[N,K]^T  (unchanged, passing)
// OUT_SPLIT=1 applies 0.125*log2e to q columns (attention runs in exp2 domain)
// ---------------------------------------------------------------------------
#define GOFF_AH 0
#define GOFF_AL 8192
#define GOFF_BH 16384
#define GOFF_BL 24576
#define GBUF    32768
#define GSMEM_BYTES (3 * GBUF + 1024)
#define QSCALE  0.18033688f   // 0.125 * log2(e)

template <int OUT_SPLIT>
__global__ __launch_bounds__(256, 2)
void gemm_wmma(const __nv_bfloat16* __restrict__ Ah, const __nv_bfloat16* __restrict__ Al,
               const __nv_bfloat16* __restrict__ Bh, const __nv_bfloat16* __restrict__ Bl,
               float* __restrict__ Cf,
               __nv_bfloat16* __restrict__ Ch, __nv_bfloat16* __restrict__ Cl,
               int M, int N, int K) {
    extern __shared__ char dsm[];
    const int tid = threadIdx.x;
    const int wid = tid >> 5;
    const int lane = tid & 31;
    const int wm = wid & 3;
    const int wn = wid >> 2;
    const int bm = blockIdx.y * 128;
    const int bn = blockIdx.x * 128;

    uint32_t rawb = smem_u32(dsm);
    uint32_t sb = (rawb + 1023u) & ~1023u;

    const int mat = lane >> 3;
    const int lr = lane & 7;
    const int aRow0 = wm * 32 + (mat & 1) * 8 + lr;
    const int aKoff = (mat >> 1) * 16;
    const int bRow0 = wn * 64 + (mat >> 1) * 8 + lr;
    const int bKoff = (mat & 1) * 16;

    float acc[2][8][4];
#pragma unroll
    for (int mt = 0; mt < 2; mt++)
#pragma unroll
        for (int nt = 0; nt < 8; nt++)
#pragma unroll
            for (int e = 0; e < 4; e++) acc[mt][nt][e] = 0.f;

    const int nch = K >> 5;

#define LOAD_CHUNK(bufbase, k0_)                                                   \
    do {                                                                           \
        const char* gah = (const char*)(Ah + (size_t)bm * K + (k0_));              \
        const char* gal = (const char*)(Al + (size_t)bm * K + (k0_));              \
        const char* gbh = (const char*)(Bh + (size_t)bn * K + (k0_));              \
        const char* gbl = (const char*)(Bl + (size_t)bn * K + (k0_));              \
        _Pragma("unroll")                                                          \
        for (int i_ = 0; i_ < 2; i_++) {                                           \
            int idx_ = tid + i_ * 256;                                             \
            int row_ = idx_ >> 2;                                                  \
            int cc_ = idx_ & 3;                                                    \
            uint32_t so_ = SWZ64((uint32_t)(row_ * 64 + cc_ * 16));                \
            size_t go_ = (size_t)row_ * K * 2 + cc_ * 16;                          \
            CP_ASYNC16((bufbase) + GOFF_AH + so_, gah + go_);                      \
            CP_ASYNC16((bufbase) + GOFF_AL + so_, gal + go_);                      \
            CP_ASYNC16((bufbase) + GOFF_BH + so_, gbh + go_);                      \
            CP_ASYNC16((bufbase) + GOFF_BL + so_, gbl + go_);                      \
        }                                                                          \
    } while (0)

    LOAD_CHUNK(sb, 0);
    CP_COMMIT();
    LOAD_CHUNK(sb + GBUF, 32);
    CP_COMMIT();

    for (int c = 0; c < nch; c++) {
        if (c + 1 < nch) { CP_WAIT(1); } else { CP_WAIT(0); }
        __syncthreads();
        if (c + 2 < nch) {
            int nb = (c + 2) % 3;
            LOAD_CHUNK(sb + nb * GBUF, (c + 2) << 5);
            CP_COMMIT();
        }

        const uint32_t cbuf = sb + (c % 3) * GBUF;
#pragma unroll
        for (int ks = 0; ks < 2; ks++) {
            uint32_t afh[2][4], afl[2][4], bfh[4][4], bfl[4][4];
#pragma unroll
            for (int mt = 0; mt < 2; mt++) {
                uint32_t off = SWZ64((uint32_t)((aRow0 + mt * 16) * 64 + ks * 32 + aKoff));
                LDSM_X4(afh[mt], cbuf + GOFF_AH + off);
                LDSM_X4(afl[mt], cbuf + GOFF_AL + off);
            }
#pragma unroll
            for (int np = 0; np < 4; np++) {
                uint32_t off = SWZ64((uint32_t)((bRow0 + np * 16) * 64 + ks * 32 + bKoff));
                LDSM_X4(bfh[np], cbuf + GOFF_BH + off);
                LDSM_X4(bfl[np], cbuf + GOFF_BL + off);
            }
            // term-major passes: same-acc reuse distance = 16
#pragma unroll
            for (int mt = 0; mt < 2; mt++)
#pragma unroll
                for (int nt = 0; nt < 8; nt++) {
                    const int np = nt >> 1, s = (nt & 1) * 2;
                    MMA16816(acc[mt][nt], afh[mt], bfh[np][s], bfh[np][s + 1]);
                }
#pragma unroll
            for (int mt = 0; mt < 2; mt++)
#pragma unroll
                for (int nt = 0; nt < 8; nt++) {
                    const int np = nt >> 1, s = (nt & 1) * 2;
                    MMA16816(acc[mt][nt], afh[mt], bfl[np][s], bfl[np][s + 1]);
                }
#pragma unroll
            for (int mt = 0; mt < 2; mt++)
#pragma unroll
                for (int nt = 0; nt < 8; nt++) {
                    const int np = nt >> 1, s = (nt & 1) * 2;
                    MMA16816(acc[mt][nt], afl[mt], bfh[np][s], bfh[np][s + 1]);
                }
        }
    }

    const int erow = bm + wm * 32 + (lane >> 2);
    const int ecol = bn + wn * 64 + (lane & 3) * 2;
#pragma unroll
    for (int mt = 0; mt < 2; mt++)
#pragma unroll
        for (int nt = 0; nt < 8; nt++) {
            if (OUT_SPLIT) {
                const float sc = (ecol + nt * 8 < C_) ? QSCALE : 1.0f;
                uint32_t hi, lo;
                size_t o0 = (size_t)(erow + mt * 16) * N + ecol + nt * 8;
                split2(acc[mt][nt][0] * sc, acc[mt][nt][1] * sc, hi, lo);
                *(uint32_t*)(Ch + o0) = hi;
                *(uint32_t*)(Cl + o0) = lo;
                split2(acc[mt][nt][2] * sc, acc[mt][nt][3] * sc, hi, lo);
                *(uint32_t*)(Ch + o0 + (size_t)8 * N) = hi;
                *(uint32_t*)(Cl + o0 + (size_t)8 * N) = lo;
            } else {
                float* p = Cf + (size_t)(erow + mt * 16) * N + ecol + nt * 8;
                *(float2*)p = make_float2(acc[mt][nt][0], acc[mt][nt][1]);
                *(float2*)(p + (size_t)8 * N) = make_float2(acc[mt][nt][2], acc[mt][nt][3]);
            }
        }
#undef LOAD_CHUNK
}

// ---------------------------------------------------------------------------
// Flash attention (R14 base: 256 thr, 8 warps x 16 rows, Q hoisted, term-major,
// ex2 softmax, 1 CTA/SM) with 128-KEY TILES: per-tile fixed costs (barrier,
// shuffle reductions, oacc rescale, staging issue) halve; MMA/ex2 per key
// unchanged. smem = Q 36.9K + 2 x 73.7K = 185.3KB. Regs ~215 < 255 (no cap).
// ---------------------------------------------------------------------------
#define RS   144
#define AT_QH   0
#define AT_QL   18432
#define AT_KV0  36864
#define AT_KH   0
#define AT_KL   18432
#define AT_VH   36864
#define AT_VL   55296
#define AT_KVBUF 73728
#define AT_SMEM_ALLOC (AT_KV0 + 2 * AT_KVBUF + 1024)   // 185344

__global__ __launch_bounds__(256, 1)
void attn_mma(const __nv_bfloat16* __restrict__ qh, const __nv_bfloat16* __restrict__ ql,
              __nv_bfloat16* __restrict__ oh, __nv_bfloat16* __restrict__ ol) {
    extern __shared__ char dsm[];
    const int tid = threadIdx.x;
    const int wid = tid >> 5;
    const int l = tid & 31;
    const int qi = 15 - (int)blockIdx.x;        // longest first
    const int h = blockIdx.y;
    const int b = blockIdx.z;

    uint32_t sb = (smem_u32(dsm) + 1023u) & ~1023u;

    const size_t gq0 = ((size_t)(b * T_ + qi * 128) * C3_ + h * DH_) * 2;  // byte off
    const char* gqh = (const char*)qh + gq0;
    const char* gql = (const char*)ql + gq0;

    // Stage Q (128 rows x 128B), hi + lo -> group 0
#pragma unroll
    for (int i = 0; i < 4; i++) {
        int idx = tid + i * 256;
        int row = idx >> 3;
        int c = (idx & 7) * 16;
        CP_ASYNC16(sb + AT_QH + row * RS + c, gqh + (size_t)row * GROWB + c);
        CP_ASYNC16(sb + AT_QL + row * RS + c, gql + (size_t)row * GROWB + c);
    }
    CP_COMMIT();

    const int nkt = qi + 1;   // 128-key tiles, >= 1

    // Stage one 128-key KV tile (K hi/lo + V hi/lo), 16 cp.async per thread
#define STAGE_KV(kt_, buf_)                                                        \
    do {                                                                           \
        uint32_t base_ = sb + AT_KV0 + (buf_) * AT_KVBUF;                          \
        size_t g0_ = ((size_t)(b * T_ + (kt_) * 128) * C3_ + h * DH_ + C_) * 2;    \
        const char* gkh_ = (const char*)qh + g0_;                                  \
        const char* gkl_ = (const char*)ql + g0_;                                  \
        _Pragma("unroll")                                                          \
        for (int i_ = 0; i_ < 4; i_++) {                                           \
            int idx_ = tid + i_ * 256;                                             \
            int row_ = idx_ >> 3;                                                  \
            int c_ = (idx_ & 7) * 16;                                              \
            size_t go_ = (size_t)row_ * GROWB + c_;                                \
            CP_ASYNC16(base_ + AT_KH + row_ * RS + c_, gkh_ + go_);                \
            CP_ASYNC16(base_ + AT_KL + row_ * RS + c_, gkl_ + go_);                \
            CP_ASYNC16(base_ + AT_VH + row_ * RS + c_, gkh_ + go_ + 2 * C_);       \
            CP_ASYNC16(base_ + AT_VL + row_ * RS + c_, gkl_ + go_ + 2 * C_);       \
        }                                                                          \
    } while (0)

    STAGE_KV(0, 0);
    CP_COMMIT();

    float so[16][4], oacc[8][4];
    float m0 = -1e30f, m1 = -1e30f, l0 = 0.f, l1 = 0.f;
#pragma unroll
    for (int nt = 0; nt < 8; nt++)
#pragma unroll
        for (int e = 0; e < 4; e++) oacc[nt][e] = 0.f;

    // ldmatrix address components
    const int mat = l >> 3;
    const uint32_t aAddr0 = sb + AT_QH + (wid * 16 + (mat & 1) * 8 + (l & 7)) * RS + (mat >> 1) * 16;
    const uint32_t bRow = (mat >> 1) * 8 + (l & 7);      // + np*16 rows (0..127)
    const uint32_t bKo = (mat & 1) * 16;
    const uint32_t vRow = l & 15;                         // + ks*16 rows (0..127)
    const uint32_t vCo = (l >> 4) * 16;                   // + np*32 bytes

    // Hoist Q fragments (loop-invariant). Pending groups: {Q, KV0}.
    CP_WAIT(1);
    __syncthreads();
    uint32_t aqh[4][4], aql[4][4];
#pragma unroll
    for (int ks = 0; ks < 4; ks++) {
        LDSM_X4(aqh[ks], aAddr0 + ks * 32);
        LDSM_X4(aql[ks], aAddr0 + ks * 32 + (AT_QL - AT_QH));
    }

    for (int kt = 0; kt < nkt; kt++) {
        CP_WAIT(0);
        __syncthreads();   // all warps done reading the buffer being restaged
        if (kt + 1 < nkt) {
            STAGE_KV(kt + 1, (kt + 1) & 1);
            CP_COMMIT();
        }
        const uint32_t kvb = sb + AT_KV0 + (kt & 1) * AT_KVBUF;

        // ---- S = Q K^T (x3 split), term-major in half-blocks of 4 np ----
#pragma unroll
        for (int nt = 0; nt < 16; nt++)
#pragma unroll
            for (int e = 0; e < 4; e++) so[nt][e] = 0.f;

#pragma unroll
        for (int ks = 0; ks < 4; ks++) {
#pragma unroll
            for (int half = 0; half < 2; half++) {
                uint32_t bh[4][4], bl[4][4];
#pragma unroll
                for (int j = 0; j < 4; j++) {
                    int np = half * 4 + j;
                    uint32_t off = kvb + (np * 16 + bRow) * RS + ks * 32 + bKo;
                    LDSM_X4(bh[j], off + AT_KH);
                    LDSM_X4(bl[j], off + AT_KL);
                }
#pragma unroll
                for (int j = 0; j < 4; j++) {
                    int np = half * 4 + j;
                    MMA16816(so[2 * np],     aqh[ks], bh[j][0], bh[j][1]);
                    MMA16816(so[2 * np + 1], aqh[ks], bh[j][2], bh[j][3]);
                }
#pragma unroll
                for (int j = 0; j < 4; j++) {
                    int np = half * 4 + j;
                    MMA16816(so[2 * np],     aqh[ks], bl[j][0], bl[j][1]);
                    MMA16816(so[2 * np + 1], aqh[ks], bl[j][2], bl[j][3]);
                }
#pragma unroll
                for (int j = 0; j < 4; j++) {
                    int np = half * 4 + j;
                    MMA16816(so[2 * np],     aql[ks], bh[j][0], bh[j][1]);
                    MMA16816(so[2 * np + 1], aql[ks], bh[j][2], bh[j][3]);
                }
            }
        }

        // ---- causal mask (only the diagonal tile kt == qi) ----
        if (kt == qi) {
            const int rg0 = qi * 128 + wid * 16 + (l >> 2);
            const int kg0 = kt * 128 + (l & 3) * 2;
#pragma unroll
            for (int nt = 0; nt < 16; nt++) {
#pragma unroll
                for (int e = 0; e < 4; e++) {
                    int kg = kg0 + nt * 8 + (e & 1);
                    int rg = rg0 + ((e >> 1) << 3);
                    if (kg > rg) so[nt][e] = -1e30f;
                }
            }
        }

        // ---- online softmax, exp2 domain (scale folded into Q) ----
        float mx0 = -1e30f, mx1 = -1e30f;
#pragma unroll
        for (int nt = 0; nt < 16; nt++) {
            mx0 = fmaxf(mx0, fmaxf(so[nt][0], so[nt][1]));
            mx1 = fmaxf(mx1, fmaxf(so[nt][2], so[nt][3]));
        }
        mx0 = fmaxf(mx0, __shfl_xor_sync(0xffffffffu, mx0, 1));
        mx0 = fmaxf(mx0, __shfl_xor_sync(0xffffffffu, mx0, 2));
        mx1 = fmaxf(mx1, __shfl_xor_sync(0xffffffffu, mx1, 1));
        mx1 = fmaxf(mx1, __shfl_xor_sync(0xffffffffu, mx1, 2));
        const float mn0 = fmaxf(m0, mx0), mn1 = fmaxf(m1, mx1);
        const float al0 = ex2(m0 - mn0);
        const float al1 = ex2(m1 - mn1);
        m0 = mn0; m1 = mn1;

        float ps0 = 0.f, ps1 = 0.f;
#pragma unroll
        for (int nt = 0; nt < 16; nt++) {
            so[nt][0] = ex2(so[nt][0] - mn0);
            so[nt][1] = ex2(so[nt][1] - mn0);
            so[nt][2] = ex2(so[nt][2] - mn1);
            so[nt][3] = ex2(so[nt][3] - mn1);
            ps0 += so[nt][0] + so[nt][1];
            ps1 += so[nt][2] + so[nt][3];
        }
        ps0 += __shfl_xor_sync(0xffffffffu, ps0, 1);
        ps0 += __shfl_xor_sync(0xffffffffu, ps0, 2);
        ps1 += __shfl_xor_sync(0xffffffffu, ps1, 1);
        ps1 += __shfl_xor_sync(0xffffffffu, ps1, 2);
        l0 = l0 * al0 + ps0;
        l1 = l1 * al1 + ps1;
#pragma unroll
        for (int nt = 0; nt < 8; nt++) {
            oacc[nt][0] *= al0; oacc[nt][1] *= al0;
            oacc[nt][2] *= al1; oacc[nt][3] *= al1;
        }

        // ---- O += P V (x3 split), 8 k-steps of 16, term-major ----
#pragma unroll
        for (int ks = 0; ks < 8; ks++) {
            uint32_t ph[4], pl[4];
            split2(so[2 * ks][0], so[2 * ks][1], ph[0], pl[0]);
            split2(so[2 * ks][2], so[2 * ks][3], ph[1], pl[1]);
            split2(so[2 * ks + 1][0], so[2 * ks + 1][1], ph[2], pl[2]);
            split2(so[2 * ks + 1][2], so[2 * ks + 1][3], ph[3], pl[3]);
            uint32_t vh[4][4], vl[4][4];
#pragma unroll
            for (int np = 0; np < 4; np++) {
                uint32_t off = kvb + (ks * 16 + vRow) * RS + np * 32 + vCo;
                LDSM_X4_T(vh[np], off + AT_VH);
                LDSM_X4_T(vl[np], off + AT_VL);
            }
#pragma unroll
            for (int np = 0; np < 4; np++) {
                MMA16816(oacc[2 * np],     ph, vh[np][0], vh[np][1]);
                MMA16816(oacc[2 * np + 1], ph, vh[np][2], vh[np][3]);
            }
#pragma unroll
            for (int np = 0; np < 4; np++) {
                MMA16816(oacc[2 * np],     ph, vl[np][0], vl[np][1]);
                MMA16816(oacc[2 * np + 1], ph, vl[np][2], vl[np][3]);
            }
#pragma unroll
            for (int np = 0; np < 4; np++) {
                MMA16816(oacc[2 * np],     pl, vh[np][0], vh[np][1]);
                MMA16816(oacc[2 * np + 1], pl, vh[np][2], vh[np][3]);
            }
        }
    }

    // ---- normalize + write output pre-split (bf16 hi/lo) ----
    const float i0 = 1.0f / l0, i1 = 1.0f / l1;
    const int row0 = b * T_ + qi * 128 + wid * 16 + (l >> 2);
    const int col = h * DH_ + (l & 3) * 2;
#pragma unroll
    for (int nt = 0; nt < 8; nt++) {
        uint32_t hi, lo;
        size_t o0 = (size_t)row0 * C_ + col + nt * 8;
        split2(oacc[nt][0] * i0, oacc[nt][1] * i0, hi, lo);
        *(uint32_t*)(oh + o0) = hi;
        *(uint32_t*)(ol + o0) = lo;
        split2(oacc[nt][2] * i1, oacc[nt][3] * i1, hi, lo);
        *(uint32_t*)(oh + o0 + (size_t)8 * C_) = hi;
        *(uint32_t*)(ol + o0 + (size_t)8 * C_) = lo;
    }
#undef STAGE_KV
}

// ---------------------------------------------------------------------------
extern "C" void kernel_launch(void* const* d_in, const int* in_sizes, int n_in,
                              void* d_out, int out_size) {
    const float* x = nullptr;
    const float* Wqkv = nullptr;
    const float* Wout = nullptr;
    for (int i = 0; i < n_in; i++) {
        if (in_sizes[i] == B_ * T_ * C_)     x = (const float*)d_in[i];
        else if (in_sizes[i] == C_ * 3 * C_) Wqkv = (const float*)d_in[i];
        else if (in_sizes[i] == C_ * C_)     Wout = (const float*)d_in[i];
    }
    float* out = (float*)d_out;

    __nv_bfloat16 *xh, *xl, *qvh, *qvl, *ah, *al, *wqh, *wql, *woh, *wol;
    cudaGetSymbolAddress((void**)&xh, g_xh);
    cudaGetSymbolAddress((void**)&xl, g_xl);
    cudaGetSymbolAddress((void**)&qvh, g_qkvh);
    cudaGetSymbolAddress((void**)&qvl, g_qkvl);
    cudaGetSymbolAddress((void**)&ah, g_ah);
    cudaGetSymbolAddress((void**)&al, g_al);
    cudaGetSymbolAddress((void**)&wqh, g_wqTh);
    cudaGetSymbolAddress((void**)&wql, g_wqTl);
    cudaGetSymbolAddress((void**)&woh, g_woTh);
    cudaGetSymbolAddress((void**)&wol, g_woTl);

    cudaFuncSetAttribute(gemm_wmma<0>, cudaFuncAttributeMaxDynamicSharedMemorySize, GSMEM_BYTES);
    cudaFuncSetAttribute(gemm_wmma<1>, cudaFuncAttributeMaxDynamicSharedMemorySize, GSMEM_BYTES);
    cudaFuncSetAttribute(attn_mma, cudaFuncAttributeMaxDynamicSharedMemorySize, AT_SMEM_ALLOC);

    const int nx = B_ * T_ * C_;

    // 0) input split + weight transpose-splits
    split_bf16<<<(nx + 255) / 256, 256>>>(x, xh, xl, nx);
    transpose_split<<<dim3((3 * C_) / 32, C_ / 32), dim3(32, 8)>>>(Wqkv, wqh, wql, C_, 3 * C_);
    transpose_split<<<dim3(C_ / 32, C_ / 32), dim3(32, 8)>>>(Wout, woh, wol, C_, C_);

    // 1) QKV projection, bf16 hi/lo output, q block pre-scaled by 0.125*log2e
    gemm_wmma<1><<<dim3((3 * C_) / 128, (B_ * T_) / 128), 256, GSMEM_BYTES>>>(
        xh, xl, wqh, wql, nullptr, qvh, qvl, B_ * T_, 3 * C_, C_);

    // 2) Causal flash attention on tensor cores; emits pre-split output
    attn_mma<<<dim3(T_ / 128, H_, B_), 256, AT_SMEM_ALLOC>>>(qvh, qvl, ah, al);

    // 3) Output projection, fp32 out
    gemm_wmma<0><<<dim3(C_ / 128, (B_ * T_) / 128), 256, GSMEM_BYTES>>>(
        ah, al, woh, wol, out, nullptr, nullptr, B_ * T_, C_, C_);
}